// round 3
// baseline (speedup 1.0000x reference)
#include <cuda_runtime.h>
#include <cstdint>

// OccGridEmaBatched: scatter EMA-max update + binarize.
//   B=8, R=160, G = B*R^3 = 32,768,000 cells
//   new[cell] = touched ? max(old*0.95, max val over points hitting cell) : old
//   occ[cell] = new[cell] > 0.01
//
// out layout (float32, out_size = 2*G): [0:G) = new_grid, [G:2G) = occ (1.0/0.0)

#define OB 8
#define ORES 160
#define OG (OB * ORES * ORES * ORES)   // 32,768,000

// Scatter-max scratch. Zero-initialized at module load; finalize_kernel
// re-zeroes it every launch, so every graph replay starts from S == 0.
// Encoding: touched cells hold bits(val + 1.0f) >= 1.0f; untouched hold 0.
__device__ unsigned int g_scratch[OG];

__device__ __forceinline__ int grid_idx_1d(float p) {
    // match JAX: clip(((p/2 + 0.5) * 160).astype(int32), 0, 159)
    // __f*_rn blocks FMA contraction so rounding matches jnp float32 exactly.
    float f = __fmul_rn(__fadd_rn(__fmul_rn(p, 0.5f), 0.5f), 160.0f);
    int g = (int)f;                    // trunc-toward-zero == astype(int32) for f >= 0
    g = g < 0 ? 0 : g;
    g = g > (ORES - 1) ? (ORES - 1) : g;
    return g;
}

__global__ void occ_scatter_kernel(const float* __restrict__ pts,
                                   const int* __restrict__ bidx,
                                   const float* __restrict__ val,
                                   int n) {
    int i = blockIdx.x * blockDim.x + threadIdx.x;
    if (i >= n) return;
    // Front-batch all loads (4-deep MLP) before any dependent math.
    float px = __ldg(&pts[3 * i + 0]);
    float py = __ldg(&pts[3 * i + 1]);
    float pz = __ldg(&pts[3 * i + 2]);
    int   b  = __ldg(&bidx[i]);
    float v  = __ldg(&val[i]);

    int gx = grid_idx_1d(px);
    int gy = grid_idx_1d(py);
    int gz = grid_idx_1d(pz);
    int lin = ((b * ORES + gx) * ORES + gy) * ORES + gz;
    // shift by +1.0 so touched-with-val==0 is distinguishable from untouched(0).
    unsigned int enc = __float_as_uint(__fadd_rn(v, 1.0f));
    atomicMax(&g_scratch[lin], enc);
}

__global__ void occ_finalize_kernel(const float4* __restrict__ grid4,
                                    float4* __restrict__ out_grid4,
                                    float4* __restrict__ out_occ4,
                                    int n4) {
    int i = blockIdx.x * blockDim.x + threadIdx.x;
    if (i >= n4) return;

    float4 g = grid4[i];
    uint4  s = reinterpret_cast<const uint4*>(g_scratch)[i];

    float4 nv, oc;

    {
        float sv = __uint_as_float(s.x);
        float v  = (sv >= 1.0f) ? fmaxf(__fmul_rn(g.x, 0.95f), __fadd_rn(sv, -1.0f)) : g.x;
        nv.x = v; oc.x = (v > 0.01f) ? 1.0f : 0.0f;
    }
    {
        float sv = __uint_as_float(s.y);
        float v  = (sv >= 1.0f) ? fmaxf(__fmul_rn(g.y, 0.95f), __fadd_rn(sv, -1.0f)) : g.y;
        nv.y = v; oc.y = (v > 0.01f) ? 1.0f : 0.0f;
    }
    {
        float sv = __uint_as_float(s.z);
        float v  = (sv >= 1.0f) ? fmaxf(__fmul_rn(g.z, 0.95f), __fadd_rn(sv, -1.0f)) : g.z;
        nv.z = v; oc.z = (v > 0.01f) ? 1.0f : 0.0f;
    }
    {
        float sv = __uint_as_float(s.w);
        float v  = (sv >= 1.0f) ? fmaxf(__fmul_rn(g.w, 0.95f), __fadd_rn(sv, -1.0f)) : g.w;
        nv.w = v; oc.w = (v > 0.01f) ? 1.0f : 0.0f;
    }

    out_grid4[i] = nv;
    out_occ4[i]  = oc;

    // reset scratch for the next launch (keeps graph replays deterministic)
    reinterpret_cast<uint4*>(g_scratch)[i] = make_uint4(0u, 0u, 0u, 0u);
}

extern "C" void kernel_launch(void* const* d_in, const int* in_sizes, int n_in,
                              void* d_out, int out_size) {
    const float* grid = (const float*)d_in[0];   // [B,R,R,R] = G floats
    const float* pts  = (const float*)d_in[1];   // [N,3]
    const int*   bidx = (const int*)d_in[2];     // [N]
    const float* val  = (const float*)d_in[3];   // [N]

    int n = in_sizes[2];                         // N points
    float* out = (float*)d_out;                  // [0:G) new_grid, [G:2G) occ

    const int G = OG;
    const int n4 = G / 4;

    {
        int threads = 256;
        int blocks = (n + threads - 1) / threads;
        occ_scatter_kernel<<<blocks, threads>>>(pts, bidx, val, n);
    }
    {
        int threads = 256;
        int blocks = (n4 + threads - 1) / threads;
        occ_finalize_kernel<<<blocks, threads>>>(
            (const float4*)grid,
            (float4*)out,
            (float4*)(out + G),
            n4);
    }
}

// round 6
// speedup vs baseline: 1.0283x; 1.0283x over previous
#include <cuda_runtime.h>
#include <cstdint>

// OccGridEmaBatched: scatter EMA-max update + binarize.
//   B=8, R=160, G = B*R^3 = 32,768,000 cells
//   new[cell] = touched ? max(old*0.95, max val over points hitting cell) : old
//   occ[cell] = new[cell] > 0.01
//
// out layout (float32, out_size = 2*G): [0:G) = new_grid, [G:2G) = occ (1.0/0.0)

#define OB 8
#define ORES 160
#define OG (OB * ORES * ORES * ORES)   // 32,768,000

// Scatter-max scratch. Zero-initialized at module load; finalize_kernel
// re-zeroes touched entries every launch, so every graph replay starts S == 0.
// Encoding: touched cells hold float_bits(val) + 1 (integer add). For
// non-negative floats, uint order == float order and +1 is strictly
// monotonic, so atomicMax computes the float max; decode (s-1) is EXACT.
// Untouched cells hold 0 (val >= 0 => enc >= 1, so 0 is unambiguous).
__device__ unsigned int g_scratch[OG];

__device__ __forceinline__ int grid_idx_1d(float p) {
    // match JAX: clip(((p/2 + 0.5) * 160).astype(int32), 0, 159)
    // __f*_rn blocks FMA contraction so rounding matches jnp float32 exactly.
    float f = __fmul_rn(__fadd_rn(__fmul_rn(p, 0.5f), 0.5f), 160.0f);
    int g = (int)f;                    // trunc-toward-zero == astype(int32) for f >= 0
    g = g < 0 ? 0 : g;
    g = g > (ORES - 1) ? (ORES - 1) : g;
    return g;
}

__device__ __forceinline__ void scatter_one(float px, float py, float pz,
                                            int b, float v) {
    int gx = grid_idx_1d(px);
    int gy = grid_idx_1d(py);
    int gz = grid_idx_1d(pz);
    int lin = ((b * ORES + gx) * ORES + gy) * ORES + gz;
    unsigned int enc = __float_as_uint(v) + 1u;   // exact, monotonic for v >= 0
    atomicMax(&g_scratch[lin], enc);              // compiles to RED.MAX.U32 (no return)
}

// 4 points per thread: 3x float4 (pts) + int4 (bidx) + float4 (val),
// all front-batched for deep MLP before the dependent index math.
__global__ void occ_scatter_kernel(const float4* __restrict__ pts4,
                                   const int4* __restrict__ bidx4,
                                   const float4* __restrict__ val4,
                                   int nquad) {
    int t = blockIdx.x * blockDim.x + threadIdx.x;
    if (t >= nquad) return;

    float4 p0 = pts4[3 * t + 0];   // pts[12t .. 12t+3]
    float4 p1 = pts4[3 * t + 1];   // pts[12t+4 .. 12t+7]
    float4 p2 = pts4[3 * t + 2];   // pts[12t+8 .. 12t+11]
    int4   b  = bidx4[t];
    float4 v  = val4[t];

    // point 0: (p0.x, p0.y, p0.z)   point 1: (p0.w, p1.x, p1.y)
    // point 2: (p1.z, p1.w, p2.x)   point 3: (p2.y, p2.z, p2.w)
    scatter_one(p0.x, p0.y, p0.z, b.x, v.x);
    scatter_one(p0.w, p1.x, p1.y, b.y, v.y);
    scatter_one(p1.z, p1.w, p2.x, b.z, v.z);
    scatter_one(p2.y, p2.z, p2.w, b.w, v.w);
}

// tail handler for n % 4 != 0 (not expected for N = 4194304, but safe)
__global__ void occ_scatter_tail_kernel(const float* __restrict__ pts,
                                        const int* __restrict__ bidx,
                                        const float* __restrict__ val,
                                        int start, int n) {
    int i = start + blockIdx.x * blockDim.x + threadIdx.x;
    if (i >= n) return;
    scatter_one(pts[3 * i], pts[3 * i + 1], pts[3 * i + 2], bidx[i], val[i]);
}

__global__ void occ_finalize_kernel(const float4* __restrict__ grid4,
                                    float4* __restrict__ out_grid4,
                                    float4* __restrict__ out_occ4,
                                    int n4) {
    int i = blockIdx.x * blockDim.x + threadIdx.x;
    if (i >= n4) return;

    float4 g = grid4[i];
    uint4  s = reinterpret_cast<const uint4*>(g_scratch)[i];

    float4 nv, oc;

    {
        float v = (s.x != 0u)
                    ? fmaxf(__fmul_rn(g.x, 0.95f), __uint_as_float(s.x - 1u))
                    : g.x;
        nv.x = v; oc.x = (v > 0.01f) ? 1.0f : 0.0f;
    }
    {
        float v = (s.y != 0u)
                    ? fmaxf(__fmul_rn(g.y, 0.95f), __uint_as_float(s.y - 1u))
                    : g.y;
        nv.y = v; oc.y = (v > 0.01f) ? 1.0f : 0.0f;
    }
    {
        float v = (s.z != 0u)
                    ? fmaxf(__fmul_rn(g.z, 0.95f), __uint_as_float(s.z - 1u))
                    : g.z;
        nv.z = v; oc.z = (v > 0.01f) ? 1.0f : 0.0f;
    }
    {
        float v = (s.w != 0u)
                    ? fmaxf(__fmul_rn(g.w, 0.95f), __uint_as_float(s.w - 1u))
                    : g.w;
        nv.w = v; oc.w = (v > 0.01f) ? 1.0f : 0.0f;
    }

    out_grid4[i] = nv;
    out_occ4[i]  = oc;

    // Reset scratch for the next launch, but only where it was touched
    // (untouched uint4s are already zero) — saves ~60% of the reset writes.
    if (s.x | s.y | s.z | s.w) {
        reinterpret_cast<uint4*>(g_scratch)[i] = make_uint4(0u, 0u, 0u, 0u);
    }
}

extern "C" void kernel_launch(void* const* d_in, const int* in_sizes, int n_in,
                              void* d_out, int out_size) {
    const float* grid = (const float*)d_in[0];   // [B,R,R,R] = G floats
    const float* pts  = (const float*)d_in[1];   // [N,3]
    const int*   bidx = (const int*)d_in[2];     // [N]
    const float* val  = (const float*)d_in[3];   // [N]

    int n = in_sizes[2];                         // N points
    float* out = (float*)d_out;                  // [0:G) new_grid, [G:2G) occ

    const int G = OG;
    const int n4 = G / 4;
    const int nquad = n / 4;

    if (nquad > 0) {
        int threads = 256;
        int blocks = (nquad + threads - 1) / threads;
        occ_scatter_kernel<<<blocks, threads>>>(
            (const float4*)pts, (const int4*)bidx, (const float4*)val, nquad);
    }
    if (n % 4) {
        int start = nquad * 4;
        occ_scatter_tail_kernel<<<1, 256>>>(pts, bidx, val, start, n);
    }
    {
        int threads = 256;
        int blocks = (n4 + threads - 1) / threads;
        occ_finalize_kernel<<<blocks, threads>>>(
            (const float4*)grid,
            (float4*)out,
            (float4*)(out + G),
            n4);
    }
}

// round 7
// speedup vs baseline: 1.0409x; 1.0122x over previous
#include <cuda_runtime.h>
#include <cstdint>

// OccGridEmaBatched: scatter EMA-max update + binarize.
//   B=8, R=160, G = B*R^3 = 32,768,000 cells
//   new[cell] = touched ? max(old*0.95, max val over points hitting cell) : old
//   occ[cell] = new[cell] > 0.01
//
// out layout (float32, out_size = 2*G): [0:G) = new_grid, [G:2G) = occ (1.0/0.0)

#define OB 8
#define ORES 160
#define OG (OB * ORES * ORES * ORES)   // 32,768,000

// Scatter-max scratch. Zero-initialized at module load; finalize_kernel
// re-zeroes touched entries every launch, so every graph replay starts S == 0.
// Encoding: touched cells hold float_bits(val) + 1 (integer add). For
// non-negative floats, uint order == float order and +1 is strictly
// monotonic, so atomicMax computes the float max; decode (s-1) is EXACT.
// Untouched cells hold 0 (val >= 0 => enc >= 1, so 0 is unambiguous).
__device__ unsigned int g_scratch[OG];

__device__ __forceinline__ int grid_idx_1d(float p) {
    // match JAX: clip(((p/2 + 0.5) * 160).astype(int32), 0, 159)
    // __f*_rn blocks FMA contraction so rounding matches jnp float32 exactly.
    float f = __fmul_rn(__fadd_rn(__fmul_rn(p, 0.5f), 0.5f), 160.0f);
    int g = (int)f;                    // trunc-toward-zero == astype(int32) for f >= 0
    g = g < 0 ? 0 : g;
    g = g > (ORES - 1) ? (ORES - 1) : g;
    return g;
}

__device__ __forceinline__ void scatter_one(float px, float py, float pz,
                                            int b, float v) {
    int gx = grid_idx_1d(px);
    int gy = grid_idx_1d(py);
    int gz = grid_idx_1d(pz);
    int lin = ((b * ORES + gx) * ORES + gy) * ORES + gz;
    unsigned int enc = __float_as_uint(v) + 1u;   // exact, monotonic for v >= 0
    atomicMax(&g_scratch[lin], enc);              // compiles to RED.MAX.U32 (no return)
}

// 4 points per thread. All input loads use __ldcs (evict-first streaming):
// the inputs have ZERO reuse, so keeping them out of L2 preserves residency
// for the atomic RMW sectors (reuse ~1.6x), converting repeat atomics from
// DRAM row activations into L2 hits.
__global__ void occ_scatter_kernel(const float4* __restrict__ pts4,
                                   const int4* __restrict__ bidx4,
                                   const float4* __restrict__ val4,
                                   int nquad) {
    int t = blockIdx.x * blockDim.x + threadIdx.x;
    if (t >= nquad) return;

    float4 p0 = __ldcs(&pts4[3 * t + 0]);   // pts[12t .. 12t+3]
    float4 p1 = __ldcs(&pts4[3 * t + 1]);   // pts[12t+4 .. 12t+7]
    float4 p2 = __ldcs(&pts4[3 * t + 2]);   // pts[12t+8 .. 12t+11]
    int4   b  = __ldcs(&bidx4[t]);
    float4 v  = __ldcs(&val4[t]);

    // point 0: (p0.x, p0.y, p0.z)   point 1: (p0.w, p1.x, p1.y)
    // point 2: (p1.z, p1.w, p2.x)   point 3: (p2.y, p2.z, p2.w)
    scatter_one(p0.x, p0.y, p0.z, b.x, v.x);
    scatter_one(p0.w, p1.x, p1.y, b.y, v.y);
    scatter_one(p1.z, p1.w, p2.x, b.z, v.z);
    scatter_one(p2.y, p2.z, p2.w, b.w, v.w);
}

// tail handler for n % 4 != 0 (not expected for N = 4194304, but safe)
__global__ void occ_scatter_tail_kernel(const float* __restrict__ pts,
                                        const int* __restrict__ bidx,
                                        const float* __restrict__ val,
                                        int start, int n) {
    int i = start + blockIdx.x * blockDim.x + threadIdx.x;
    if (i >= n) return;
    scatter_one(pts[3 * i], pts[3 * i + 1], pts[3 * i + 2], bidx[i], val[i]);
}

__global__ void occ_finalize_kernel(const float4* __restrict__ grid4,
                                    float4* __restrict__ out_grid4,
                                    float4* __restrict__ out_occ4,
                                    int n4) {
    int i = blockIdx.x * blockDim.x + threadIdx.x;
    if (i >= n4) return;

    // Pure streaming pass: evict-first loads, streaming stores.
    float4 g = __ldcs(&grid4[i]);
    uint4  s = __ldcs(&reinterpret_cast<const uint4*>(g_scratch)[i]);

    float4 nv, oc;

    {
        float v = (s.x != 0u)
                    ? fmaxf(__fmul_rn(g.x, 0.95f), __uint_as_float(s.x - 1u))
                    : g.x;
        nv.x = v; oc.x = (v > 0.01f) ? 1.0f : 0.0f;
    }
    {
        float v = (s.y != 0u)
                    ? fmaxf(__fmul_rn(g.y, 0.95f), __uint_as_float(s.y - 1u))
                    : g.y;
        nv.y = v; oc.y = (v > 0.01f) ? 1.0f : 0.0f;
    }
    {
        float v = (s.z != 0u)
                    ? fmaxf(__fmul_rn(g.z, 0.95f), __uint_as_float(s.z - 1u))
                    : g.z;
        nv.z = v; oc.z = (v > 0.01f) ? 1.0f : 0.0f;
    }
    {
        float v = (s.w != 0u)
                    ? fmaxf(__fmul_rn(g.w, 0.95f), __uint_as_float(s.w - 1u))
                    : g.w;
        nv.w = v; oc.w = (v > 0.01f) ? 1.0f : 0.0f;
    }

    __stcs(&out_grid4[i], nv);
    __stcs(&out_occ4[i], oc);

    // Reset scratch for the next launch, but only where it was touched
    // (untouched uint4s are already zero) — saves ~60% of the reset writes.
    if (s.x | s.y | s.z | s.w) {
        __stcs(&reinterpret_cast<uint4*>(g_scratch)[i],
               make_uint4(0u, 0u, 0u, 0u));
    }
}

extern "C" void kernel_launch(void* const* d_in, const int* in_sizes, int n_in,
                              void* d_out, int out_size) {
    const float* grid = (const float*)d_in[0];   // [B,R,R,R] = G floats
    const float* pts  = (const float*)d_in[1];   // [N,3]
    const int*   bidx = (const int*)d_in[2];     // [N]
    const float* val  = (const float*)d_in[3];   // [N]

    int n = in_sizes[2];                         // N points
    float* out = (float*)d_out;                  // [0:G) new_grid, [G:2G) occ

    const int G = OG;
    const int n4 = G / 4;
    const int nquad = n / 4;

    if (nquad > 0) {
        int threads = 256;
        int blocks = (nquad + threads - 1) / threads;
        occ_scatter_kernel<<<blocks, threads>>>(
            (const float4*)pts, (const int4*)bidx, (const float4*)val, nquad);
    }
    if (n % 4) {
        int start = nquad * 4;
        occ_scatter_tail_kernel<<<1, 256>>>(pts, bidx, val, start, n);
    }
    {
        int threads = 256;
        int blocks = (n4 + threads - 1) / threads;
        occ_finalize_kernel<<<blocks, threads>>>(
            (const float4*)grid,
            (float4*)out,
            (float4*)(out + G),
            n4);
    }
}

// round 9
// speedup vs baseline: 1.0440x; 1.0030x over previous
#include <cuda_runtime.h>
#include <cstdint>

// OccGridEmaBatched: scatter EMA-max update + binarize.
//   B=8, R=160, G = B*R^3 = 32,768,000 cells
//   new[cell] = touched ? max(old*0.95, max val over points hitting cell) : old
//   occ[cell] = new[cell] > 0.01
//
// out layout (float32, out_size = 2*G): [0:G) = new_grid, [G:2G) = occ (1.0/0.0)

#define OB 8
#define ORES 160
#define OG (OB * ORES * ORES * ORES)   // 32,768,000

// Scatter-max scratch. Zero-initialized at module load; finalize_kernel
// re-zeroes touched entries every launch, so every graph replay starts S == 0.
// Encoding: touched cells hold float_bits(val) + 1 (integer add). For
// non-negative floats, uint order == float order and +1 is strictly
// monotonic, so atomicMax computes the float max; decode (s-1) is EXACT.
// Untouched cells hold 0 (val >= 0 => enc >= 1, so 0 is unambiguous).
__device__ unsigned int g_scratch[OG];

__device__ __forceinline__ int grid_idx_1d(float p) {
    // match JAX: clip(((p/2 + 0.5) * 160).astype(int32), 0, 159)
    // __f*_rn blocks FMA contraction so rounding matches jnp float32 exactly.
    float f = __fmul_rn(__fadd_rn(__fmul_rn(p, 0.5f), 0.5f), 160.0f);
    int g = (int)f;                    // trunc-toward-zero == astype(int32) for f >= 0
    g = g < 0 ? 0 : g;
    g = g > (ORES - 1) ? (ORES - 1) : g;
    return g;
}

__device__ __forceinline__ void scatter_one(float px, float py, float pz,
                                            int b, float v) {
    int gx = grid_idx_1d(px);
    int gy = grid_idx_1d(py);
    int gz = grid_idx_1d(pz);
    int lin = ((b * ORES + gx) * ORES + gy) * ORES + gz;
    unsigned int enc = __float_as_uint(v) + 1u;   // exact, monotonic for v >= 0
    atomicMax(&g_scratch[lin], enc);              // compiles to RED.MAX.U32 (no return)
}

// 4 points per thread. All input loads use __ldcs (evict-first streaming):
// the inputs have ZERO reuse, so keeping them out of L2 preserves residency
// for the atomic RMW sectors (reuse ~1.6x), converting repeat atomics from
// DRAM row activations into L2 hits. (Measured R7: scatter 94.7 -> 87.6 us.)
__global__ void occ_scatter_kernel(const float4* __restrict__ pts4,
                                   const int4* __restrict__ bidx4,
                                   const float4* __restrict__ val4,
                                   int nquad) {
    int t = blockIdx.x * blockDim.x + threadIdx.x;
    if (t >= nquad) return;

    float4 p0 = __ldcs(&pts4[3 * t + 0]);   // pts[12t .. 12t+3]
    float4 p1 = __ldcs(&pts4[3 * t + 1]);   // pts[12t+4 .. 12t+7]
    float4 p2 = __ldcs(&pts4[3 * t + 2]);   // pts[12t+8 .. 12t+11]
    int4   b  = __ldcs(&bidx4[t]);
    float4 v  = __ldcs(&val4[t]);

    // point 0: (p0.x, p0.y, p0.z)   point 1: (p0.w, p1.x, p1.y)
    // point 2: (p1.z, p1.w, p2.x)   point 3: (p2.y, p2.z, p2.w)
    scatter_one(p0.x, p0.y, p0.z, b.x, v.x);
    scatter_one(p0.w, p1.x, p1.y, b.y, v.y);
    scatter_one(p1.z, p1.w, p2.x, b.z, v.z);
    scatter_one(p2.y, p2.z, p2.w, b.w, v.w);
}

// tail handler for n % 4 != 0 (not expected for N = 4194304, but safe)
__global__ void occ_scatter_tail_kernel(const float* __restrict__ pts,
                                        const int* __restrict__ bidx,
                                        const float* __restrict__ val,
                                        int start, int n) {
    int i = start + blockIdx.x * blockDim.x + threadIdx.x;
    if (i >= n) return;
    scatter_one(pts[3 * i], pts[3 * i + 1], pts[3 * i + 2], bidx[i], val[i]);
}

// Finalize: plain (default-policy) loads and stores. R7 measured __ldcs/__stcs
// here as a ~5% bandwidth REGRESSION (88.3 -> 93.2 us) — the default path's
// L1/L2 write-sector merging is already optimal for this 3-stream sweep.
__global__ void occ_finalize_kernel(const float4* __restrict__ grid4,
                                    float4* __restrict__ out_grid4,
                                    float4* __restrict__ out_occ4,
                                    int n4) {
    int i = blockIdx.x * blockDim.x + threadIdx.x;
    if (i >= n4) return;

    float4 g = grid4[i];
    uint4  s = reinterpret_cast<const uint4*>(g_scratch)[i];

    float4 nv, oc;

    {
        float v = (s.x != 0u)
                    ? fmaxf(__fmul_rn(g.x, 0.95f), __uint_as_float(s.x - 1u))
                    : g.x;
        nv.x = v; oc.x = (v > 0.01f) ? 1.0f : 0.0f;
    }
    {
        float v = (s.y != 0u)
                    ? fmaxf(__fmul_rn(g.y, 0.95f), __uint_as_float(s.y - 1u))
                    : g.y;
        nv.y = v; oc.y = (v > 0.01f) ? 1.0f : 0.0f;
    }
    {
        float v = (s.z != 0u)
                    ? fmaxf(__fmul_rn(g.z, 0.95f), __uint_as_float(s.z - 1u))
                    : g.z;
        nv.z = v; oc.z = (v > 0.01f) ? 1.0f : 0.0f;
    }
    {
        float v = (s.w != 0u)
                    ? fmaxf(__fmul_rn(g.w, 0.95f), __uint_as_float(s.w - 1u))
                    : g.w;
        nv.w = v; oc.w = (v > 0.01f) ? 1.0f : 0.0f;
    }

    out_grid4[i] = nv;
    out_occ4[i]  = oc;

    // Reset scratch for the next launch, but only where it was touched
    // (untouched uint4s are already zero) — saves ~60% of the reset writes.
    if (s.x | s.y | s.z | s.w) {
        reinterpret_cast<uint4*>(g_scratch)[i] = make_uint4(0u, 0u, 0u, 0u);
    }
}

extern "C" void kernel_launch(void* const* d_in, const int* in_sizes, int n_in,
                              void* d_out, int out_size) {
    const float* grid = (const float*)d_in[0];   // [B,R,R,R] = G floats
    const float* pts  = (const float*)d_in[1];   // [N,3]
    const int*   bidx = (const int*)d_in[2];     // [N]
    const float* val  = (const float*)d_in[3];   // [N]

    int n = in_sizes[2];                         // N points
    float* out = (float*)d_out;                  // [0:G) new_grid, [G:2G) occ

    const int G = OG;
    const int n4 = G / 4;
    const int nquad = n / 4;

    if (nquad > 0) {
        int threads = 256;
        int blocks = (nquad + threads - 1) / threads;
        occ_scatter_kernel<<<blocks, threads>>>(
            (const float4*)pts, (const int4*)bidx, (const float4*)val, nquad);
    }
    if (n % 4) {
        int start = nquad * 4;
        occ_scatter_tail_kernel<<<1, 256>>>(pts, bidx, val, start, n);
    }
    {
        int threads = 256;
        int blocks = (n4 + threads - 1) / threads;
        occ_finalize_kernel<<<blocks, threads>>>(
            (const float4*)grid,
            (float4*)out,
            (float4*)(out + G),
            n4);
    }
}